// round 3
// baseline (speedup 1.0000x reference)
#include <cuda_runtime.h>
#include <cuda_bf16.h>
#include <cstdint>

#define EMB 64
#define NU 200000
#define NI 200000
#define NE 2000000
#define BATCH 16384

#define SCORE_BLOCKS 1563   // ceil((NU+NI)/256)
#define INIT_BLOCKS  512
#define GRIDA_HALF   7813   // ceil(NE/256)
#define GRIDB_HALF   1024
#define FINAL_HALF   512

// ---------------- static device scratch ----------------
__device__ int   g_slot_u[NU];
__device__ int   g_slot_i[NI];
__device__ float g_sA_u[NU];   // user . Wa_u[64:]  (dst score, user side)
__device__ float g_sB_u[NU];   // user . Wa_i[:64]  (src score, item side)
__device__ float g_sA_i[NI];   // item . Wa_u[:64]  (src score, user side)
__device__ float g_sB_i[NI];   // item . Wa_i[64:]  (dst score, item side)
__device__ float g_den_u[BATCH];
__device__ float g_den_i[BATCH];
__device__ __align__(16) float g_acc_u[BATCH * EMB];
__device__ __align__(16) float g_acc_i[BATCH * EMB];
__device__ int   g_cnt[2];
__device__ int   g_cslot[2][NE];   // compacted active edges
__device__ int   g_csrc[2][NE];
__device__ float g_cw[2][NE];

__device__ __forceinline__ void red_add_v4(float* p, float4 v) {
    asm volatile("red.global.add.v4.f32 [%0], {%1,%2,%3,%4};"
                 :: "l"(p), "f"(v.x), "f"(v.y), "f"(v.z), "f"(v.w) : "memory");
}

// ---------------- k1: init scratch + per-node attention scores (fused) ----------------
// Blocks [0,SCORE_BLOCKS): 1 thread per node, float4 streaming, Wa in shared.
// Blocks [SCORE_BLOCKS, +INIT_BLOCKS): grid-stride init of slot/den/acc/cnt.
__global__ void k1_init_scores(const float* __restrict__ user_emb,
                               const float* __restrict__ item_emb,
                               const float* __restrict__ Wa_u,
                               const float* __restrict__ Wa_i) {
    if (blockIdx.x < SCORE_BLOCKS) {
        __shared__ __align__(16) float sh[256];   // [Wa_u(128) | Wa_i(128)]
        int t = threadIdx.x;
        sh[t] = (t < 128) ? Wa_u[t] : Wa_i[t - 128];
        __syncthreads();

        int node = blockIdx.x * 256 + t;
        if (node >= NU + NI) return;
        const float* tab;
        const float4 *w1, *w2;
        float *o1, *o2;
        int n;
        if (node < NU) {
            n = node; tab = user_emb;
            w1 = (const float4*)(sh + 64);    // Wa_u[64:]
            w2 = (const float4*)(sh + 128);   // Wa_i[:64]
            o1 = g_sA_u; o2 = g_sB_u;
        } else {
            n = node - NU; tab = item_emb;
            w1 = (const float4*)(sh + 0);     // Wa_u[:64]
            w2 = (const float4*)(sh + 192);   // Wa_i[64:]
            o1 = g_sA_i; o2 = g_sB_i;
        }
        const float4* e = (const float4*)(tab + (size_t)n * EMB);
        float s1 = 0.f, s2 = 0.f;
        #pragma unroll
        for (int i = 0; i < 16; i++) {
            float4 v = e[i];
            float4 a = w1[i], b = w2[i];
            s1 += v.x * a.x + v.y * a.y + v.z * a.z + v.w * a.w;
            s2 += v.x * b.x + v.y * b.y + v.z * b.z + v.w * b.w;
        }
        o1[n] = s1; o2[n] = s2;
    } else {
        int t = (blockIdx.x - SCORE_BLOCKS) * 256 + threadIdx.x;
        int stride = INIT_BLOCKS * 256;
        if (t < 2) g_cnt[t] = 0;
        for (int n = t; n < NU; n += stride) g_slot_u[n] = -1;
        for (int n = t; n < NI; n += stride) g_slot_i[n] = -1;
        for (int n = t; n < BATCH; n += stride) { g_den_u[n] = 0.f; g_den_i[n] = 0.f; }
        for (int n = t; n < BATCH * EMB; n += stride) { g_acc_u[n] = 0.f; g_acc_i[n] = 0.f; }
    }
}

// ---------------- k2: node -> batch slot maps (dedups duplicate batch ids) ----------------
__global__ void k2_slots(const int* __restrict__ u, const int* __restrict__ i) {
    int t = blockIdx.x * blockDim.x + threadIdx.x;
    if (t < BATCH) {
        atomicCAS(&g_slot_u[u[t]], -1, t);
    } else if (t < 2 * BATCH) {
        atomicCAS(&g_slot_i[i[t - BATCH]], -1, t - BATCH);
    }
}

// ---------------- k3: phase A — scan edges, compact active ones with weights ----------------
// Max-subtraction skipped: logits bounded ~|0.6|, softmax shift-invariant (validated 1.2e-7).
__global__ void k3_edge_scan(const int* __restrict__ src0, const int* __restrict__ dst0,
                             const int* __restrict__ src1, const int* __restrict__ dst1) {
    int side = blockIdx.x >= GRIDA_HALF;
    int e = (blockIdx.x - side * GRIDA_HALF) * 256 + threadIdx.x;
    const int* src   = side ? src1     : src0;
    const int* dst   = side ? dst1     : dst0;
    const int* slot  = side ? g_slot_i : g_slot_u;
    const float* ssrc = side ? g_sB_u : g_sA_i;
    const float* sdst = side ? g_sB_i : g_sA_u;

    bool active = false;
    int s = -1, d = 0, sr = 0;
    float w = 0.f;
    if (e < NE) {
        d = dst[e];
        s = slot[d];
        sr = src[e];
        active = s >= 0;
    }
    if (active) {
        float att = ssrc[sr] + sdst[d];
        att = att > 0.f ? att : 0.01f * att;   // leaky_relu(0.01)
        w = __expf(att);
    }
    unsigned m = __ballot_sync(0xffffffffu, active);
    if (m) {
        int lane = threadIdx.x & 31;
        int leader = __ffs(m) - 1;
        int base = 0;
        if (lane == leader) base = atomicAdd(&g_cnt[side], __popc(m));
        base = __shfl_sync(0xffffffffu, base, leader);
        if (active) {
            int off = base + __popc(m & ((1u << lane) - 1u));
            g_cslot[side][off] = s;
            g_csrc[side][off]  = sr;
            g_cw[side][off]    = w;
        }
    }
}

// ---------------- k4: phase B — gather + accumulate (8 lanes/edge, 4 edges/warp) ----------
__global__ void k4_edge_gather(const float* __restrict__ feat0,
                               const float* __restrict__ feat1) {
    int side = blockIdx.x >= GRIDB_HALF;
    const float* feat = side ? feat1   : feat0;    // side0: item_emb, side1: user_emb
    float*       den  = side ? g_den_i : g_den_u;
    float*       acc  = side ? g_acc_i : g_acc_u;
    const int*   csl  = g_cslot[side];
    const int*   csr  = g_csrc[side];
    const float* cw   = g_cw[side];
    int cnt = g_cnt[side];

    int lane = threadIdx.x & 31;
    int sub  = lane & 7;                 // 0..7: which 8-float chunk of the 64-dim row
    int warp = ((blockIdx.x - side * GRIDB_HALF) * 256 + threadIdx.x) >> 5;
    int nwarps = (GRIDB_HALF * 256) >> 5;
    int ngroups = (cnt + 3) >> 2;

    for (int g = warp; g < ngroups; g += nwarps) {
        int eidx = g * 4 + (lane >> 3);
        if (eidx < cnt) {
            int   sl = csl[eidx];
            int   sr = csr[eidx];
            float w  = cw[eidx];
            const float4* fp = (const float4*)(feat + (size_t)sr * EMB);
            float4 f0 = fp[sub * 2];
            float4 f1 = fp[sub * 2 + 1];
            red_add_v4(&acc[(size_t)sl * EMB + sub * 8],
                       make_float4(w * f0.x, w * f0.y, w * f0.z, w * f0.w));
            red_add_v4(&acc[(size_t)sl * EMB + sub * 8 + 4],
                       make_float4(w * f1.x, w * f1.y, w * f1.z, w * f1.w));
            if (sub == 0) atomicAdd(&den[sl], w);
        }
    }
}

// ---------------- k5: fused per-row MLP (both sides, one launch) ----------------
__device__ __forceinline__ float2 matvec64(const float* sWT, float xlo, float xhi,
                                           float b0, float b1, int lane) {
    float a0 = b0, a1 = b1;
    #pragma unroll
    for (int k = 0; k < 32; k++) {
        float xk = __shfl_sync(0xffffffffu, xlo, k);
        a0 += xk * sWT[k * 64 + lane];
        a1 += xk * sWT[k * 64 + lane + 32];
    }
    #pragma unroll
    for (int k = 0; k < 32; k++) {
        float xk = __shfl_sync(0xffffffffu, xhi, k);
        a0 += xk * sWT[(k + 32) * 64 + lane];
        a1 += xk * sWT[(k + 32) * 64 + lane + 32];
    }
    return make_float2(a0, a1);
}

__global__ void k5_final(const int* __restrict__ u, const int* __restrict__ iid,
                         const float* __restrict__ user_emb, const float* __restrict__ item_emb,
                         const float* __restrict__ Ws_u, const float* __restrict__ bs_u,
                         const float* __restrict__ Ws_i, const float* __restrict__ bs_i,
                         const float* __restrict__ Wn_u, const float* __restrict__ bn_u,
                         const float* __restrict__ Wn_i, const float* __restrict__ bn_i,
                         const float* __restrict__ Wfc_u, const float* __restrict__ Wfc_i,
                         float* __restrict__ out) {
    int side = blockIdx.x >= FINAL_HALF;
    const int*   ids     = side ? iid      : u;
    const float* emb_tab = side ? item_emb : user_emb;
    const float* Ws  = side ? Ws_i  : Ws_u;
    const float* bs  = side ? bs_i  : bs_u;
    const float* Wn  = side ? Wn_i  : Wn_u;
    const float* bn  = side ? bn_i  : bn_u;
    const float* Wfc = side ? Wfc_i : Wfc_u;
    const int*   slot = side ? g_slot_i : g_slot_u;
    const float* den  = side ? g_den_i  : g_den_u;
    const float* acc  = side ? g_acc_i  : g_acc_u;
    const int col_off = side ? 64 : 0;

    extern __shared__ float sh[];
    float* sWsT  = sh;                  // 64*64
    float* sWnT  = sh + 64 * 64;        // 64*64
    float* sWfcT = sh + 2 * 64 * 64;    // 128*64
    for (int idx = threadIdx.x; idx < 64 * 64; idx += blockDim.x) {
        int j = idx >> 6, k = idx & 63;
        sWsT[k * 64 + j] = Ws[idx];
        sWnT[k * 64 + j] = Wn[idx];
    }
    for (int idx = threadIdx.x; idx < 64 * 128; idx += blockDim.x) {
        int j = idx >> 7, k = idx & 127;
        sWfcT[k * 64 + j] = Wfc[idx];
    }
    __syncthreads();

    int lane = threadIdx.x & 31;
    int warp = ((blockIdx.x - side * FINAL_HALF) * 256 + threadIdx.x) >> 5;
    int nwarps = (FINAL_HALF * 256) >> 5;
    float b_s0 = bs[lane], b_s1 = bs[lane + 32];
    float b_n0 = bn[lane], b_n1 = bn[lane + 32];

    for (int b = warp; b < BATCH; b += nwarps) {
        int node = ids[b];
        int s = slot[node];
        float dv = den[s];
        float inv = dv > 0.f ? 1.f / dv : 0.f;   // empty segment -> h = 0 (matches ref)
        float hlo = acc[(size_t)s * EMB + lane] * inv;
        float hhi = acc[(size_t)s * EMB + 32 + lane] * inv;
        float elo = emb_tab[(size_t)node * EMB + lane];
        float ehi = emb_tab[(size_t)node * EMB + 32 + lane];

        float2 sf = matvec64(sWsT, elo, ehi, b_s0, b_s1, lane);
        float2 nb = matvec64(sWnT, hlo, hhi, b_n0, b_n1, lane);
        float sf0 = fmaxf(sf.x, 0.f), sf1 = fmaxf(sf.y, 0.f);
        float nb0 = fmaxf(nb.x, 0.f), nb1 = fmaxf(nb.y, 0.f);

        float a0 = 0.f, a1 = 0.f;
        #pragma unroll
        for (int k = 0; k < 32; k++) {
            float xk = __shfl_sync(0xffffffffu, sf0, k);
            a0 += xk * sWfcT[k * 64 + lane];
            a1 += xk * sWfcT[k * 64 + lane + 32];
        }
        #pragma unroll
        for (int k = 0; k < 32; k++) {
            float xk = __shfl_sync(0xffffffffu, sf1, k);
            a0 += xk * sWfcT[(k + 32) * 64 + lane];
            a1 += xk * sWfcT[(k + 32) * 64 + lane + 32];
        }
        #pragma unroll
        for (int k = 0; k < 32; k++) {
            float xk = __shfl_sync(0xffffffffu, nb0, k);
            a0 += xk * sWfcT[(k + 64) * 64 + lane];
            a1 += xk * sWfcT[(k + 64) * 64 + lane + 32];
        }
        #pragma unroll
        for (int k = 0; k < 32; k++) {
            float xk = __shfl_sync(0xffffffffu, nb1, k);
            a0 += xk * sWfcT[(k + 96) * 64 + lane];
            a1 += xk * sWfcT[(k + 96) * 64 + lane + 32];
        }
        out[(size_t)b * 128 + col_off + lane]      = fmaxf(a0, 0.f);
        out[(size_t)b * 128 + col_off + 32 + lane] = fmaxf(a1, 0.f);
    }
}

// ---------------- launch ----------------
extern "C" void kernel_launch(void* const* d_in, const int* in_sizes, int n_in,
                              void* d_out, int out_size) {
    const float* user_emb = (const float*)d_in[0];
    const float* item_emb = (const float*)d_in[1];
    const float* Wa_u = (const float*)d_in[2];
    const float* Wa_i = (const float*)d_in[3];
    const float* Wfc_u = (const float*)d_in[4];
    const float* Wfc_i = (const float*)d_in[5];
    const float* Ws_u = (const float*)d_in[6];
    const float* bs_u = (const float*)d_in[7];
    const float* Ws_i = (const float*)d_in[8];
    const float* bs_i = (const float*)d_in[9];
    const float* Wn_u = (const float*)d_in[10];
    const float* bn_u = (const float*)d_in[11];
    const float* Wn_i = (const float*)d_in[12];
    const float* bn_i = (const float*)d_in[13];
    const int* u      = (const int*)d_in[14];
    const int* iid    = (const int*)d_in[15];
    const int* src_iu = (const int*)d_in[16];
    const int* dst_iu = (const int*)d_in[17];
    const int* src_ui = (const int*)d_in[18];
    const int* dst_ui = (const int*)d_in[19];
    float* out = (float*)d_out;

    const int SMEM_FINAL = (2 * 64 * 64 + 128 * 64) * sizeof(float);  // 65536 B
    static bool attr_set = false;
    if (!attr_set) {
        cudaFuncSetAttribute(k5_final, cudaFuncAttributeMaxDynamicSharedMemorySize, SMEM_FINAL);
        attr_set = true;
    }

    k1_init_scores<<<SCORE_BLOCKS + INIT_BLOCKS, 256>>>(user_emb, item_emb, Wa_u, Wa_i);
    k2_slots<<<(2 * BATCH + 255) / 256, 256>>>(u, iid);
    k3_edge_scan<<<2 * GRIDA_HALF, 256>>>(src_iu, dst_iu, src_ui, dst_ui);
    k4_edge_gather<<<2 * GRIDB_HALF, 256>>>(item_emb, user_emb);
    k5_final<<<2 * FINAL_HALF, 256, SMEM_FINAL>>>(u, iid, user_emb, item_emb,
                                                  Ws_u, bs_u, Ws_i, bs_i,
                                                  Wn_u, bn_u, Wn_i, bn_i,
                                                  Wfc_u, Wfc_i, out);
}

// round 5
// speedup vs baseline: 1.0935x; 1.0935x over previous
#include <cuda_runtime.h>
#include <cuda_bf16.h>
#include <cstdint>

#define EMB 64
#define NU 200000
#define NI 200000
#define NE 2000000
#define BATCH 16384

#define GRID_SCAN_HALF   7813    // ceil(NE/256)
#define GRID_GATHER_HALF 2048
#define FINAL_HALF       512

// ---------------- static device scratch ----------------
__device__ int   g_slot_u[NU];
__device__ int   g_slot_i[NI];
__device__ float g_sdstb[2][BATCH];          // dst score per batch slot
__device__ float g_den_u[BATCH];
__device__ float g_den_i[BATCH];
__device__ __align__(16) float g_acc_u[BATCH * EMB];
__device__ __align__(16) float g_acc_i[BATCH * EMB];
__device__ int   g_cnt[2];
__device__ int4  g_rec[2][NE];               // {src, slot, bits(s_dst), pad}

__device__ __forceinline__ void red_add_v4(float* p, float4 v) {
    asm volatile("red.global.add.v4.f32 [%0], {%1,%2,%3,%4};"
                 :: "l"(p), "f"(v.x), "f"(v.y), "f"(v.z), "f"(v.w) : "memory");
}

// ---------------- k_init: zero scratch ----------------
__global__ void k_init() {
    int t = blockIdx.x * blockDim.x + threadIdx.x;
    int stride = gridDim.x * blockDim.x;
    if (t < 2) g_cnt[t] = 0;
    for (int n = t; n < NU; n += stride) g_slot_u[n] = -1;
    for (int n = t; n < NI; n += stride) g_slot_i[n] = -1;
    for (int n = t; n < BATCH; n += stride) { g_den_u[n] = 0.f; g_den_i[n] = 0.f; }
    float4 z = make_float4(0.f, 0.f, 0.f, 0.f);
    for (int n = t; n < BATCH * EMB / 4; n += stride) {
        ((float4*)g_acc_u)[n] = z;
        ((float4*)g_acc_i)[n] = z;
    }
}

// ---------------- k_slots: node -> batch slot (dedups duplicate ids) ----------------
__global__ void k_slots(const int* __restrict__ u, const int* __restrict__ i) {
    int t = blockIdx.x * blockDim.x + threadIdx.x;
    if (t < BATCH) {
        atomicCAS(&g_slot_u[u[t]], -1, t);
    } else if (t < 2 * BATCH) {
        atomicCAS(&g_slot_i[i[t - BATCH]], -1, t - BATCH);
    }
}

// ---------------- k_bscores: dst scores for batch nodes only (8 lanes/row) -----------
// side0: s_dst = user_emb[u[b]] . Wa_u[64:128];  side1: item_emb[i[b]] . Wa_i[64:128]
__global__ void k_bscores(const float* __restrict__ user_emb,
                          const float* __restrict__ item_emb,
                          const float* __restrict__ Wa_u,
                          const float* __restrict__ Wa_i,
                          const int* __restrict__ u, const int* __restrict__ iid) {
    int side = blockIdx.x >= 512;
    const float* tab = side ? item_emb : user_emb;
    const float* wa  = (side ? Wa_i : Wa_u) + 64;
    const int*   ids = side ? iid : u;
    int t = (blockIdx.x - side * 512) * 256 + threadIdx.x;
    int b = t >> 3, sub = t & 7;                 // 512*256/8 = 16384 rows exactly
    float4 wv0 = ((const float4*)wa)[sub * 2];
    float4 wv1 = ((const float4*)wa)[sub * 2 + 1];
    int node = ids[b];
    const float4* fp = (const float4*)(tab + (size_t)node * EMB);
    float4 f0 = fp[sub * 2], f1 = fp[sub * 2 + 1];
    float dv = f0.x * wv0.x + f0.y * wv0.y + f0.z * wv0.z + f0.w * wv0.w
             + f1.x * wv1.x + f1.y * wv1.y + f1.z * wv1.z + f1.w * wv1.w;
    #pragma unroll
    for (int o = 4; o; o >>= 1) dv += __shfl_xor_sync(0xffffffffu, dv, o);
    if (sub == 0) g_sdstb[side][b] = dv;
}

// ---------------- k_scan: compact active edges into 16B records (both sides) ---------
__global__ void k_scan(const int* __restrict__ src0, const int* __restrict__ dst0,
                       const int* __restrict__ src1, const int* __restrict__ dst1) {
    int side = blockIdx.x >= GRID_SCAN_HALF;
    const int* src  = side ? src1     : src0;
    const int* dst  = side ? dst1     : dst0;
    const int* slot = side ? g_slot_i : g_slot_u;
    int e = (blockIdx.x - side * GRID_SCAN_HALF) * 256 + threadIdx.x;

    bool act = false;
    int s = -1, sr = 0;
    float sd = 0.f;
    if (e < NE) {
        int d = dst[e];
        sr = src[e];              // unconditional: keep the load coalesced
        s = slot[d];
        act = s >= 0;
        if (act) sd = g_sdstb[side][s];
    }
    unsigned m = __ballot_sync(0xffffffffu, act);
    if (m) {
        int lane = threadIdx.x & 31;
        int leader = __ffs(m) - 1;
        int base = 0;
        if (lane == leader) base = atomicAdd(&g_cnt[side], __popc(m));
        base = __shfl_sync(0xffffffffu, base, leader);
        if (act) {
            int off = base + __popc(m & ((1u << lane) - 1u));
            g_rec[side][off] = make_int4(sr, s, __float_as_int(sd), 0);
        }
    }
}

// ---------------- k_gather: gather row, compute src score inline, accumulate --------
// 8 lanes/edge, 4 edges/warp. w = exp(leaky(row.wa_src + s_dst)); acc += w*row; den += w.
__global__ void k_gather(const float* __restrict__ feat0, const float* __restrict__ feat1,
                         const float* __restrict__ Wa_u, const float* __restrict__ Wa_i) {
    int side = blockIdx.x >= GRID_GATHER_HALF;
    const float* feat = side ? feat1   : feat0;     // side0: item_emb, side1: user_emb
    const float* wa   = side ? Wa_i    : Wa_u;      // src half = wa[0:64]
    float*       den  = side ? g_den_i : g_den_u;
    float*       acc  = side ? g_acc_i : g_acc_u;
    const int4*  rec  = g_rec[side];
    int cnt = g_cnt[side];
    if (cnt == 0) return;

    int lane = threadIdx.x & 31, sub = lane & 7;
    float4 wv0 = ((const float4*)wa)[sub * 2];      // this lane's 8-float chunk of wa_src
    float4 wv1 = ((const float4*)wa)[sub * 2 + 1];
    int warp = ((blockIdx.x - side * GRID_GATHER_HALF) * 256 + threadIdx.x) >> 5;
    int nwarps = (GRID_GATHER_HALF * 256) >> 5;
    int ngroups = (cnt + 3) >> 2;

    for (int g = warp; g < ngroups; g += nwarps) {
        int eidx = g * 4 + (lane >> 3);
        bool valid = eidx < cnt;
        int ec = valid ? eidx : cnt - 1;            // clamp: keep all lanes in the shfl
        int4 r = rec[ec];
        int sr = r.x, sl = r.y;
        float sd = __int_as_float(r.z);
        const float4* fp = (const float4*)(feat + (size_t)sr * EMB);
        float4 f0 = fp[sub * 2], f1 = fp[sub * 2 + 1];
        float dv = f0.x * wv0.x + f0.y * wv0.y + f0.z * wv0.z + f0.w * wv0.w
                 + f1.x * wv1.x + f1.y * wv1.y + f1.z * wv1.z + f1.w * wv1.w;
        #pragma unroll
        for (int o = 4; o; o >>= 1) dv += __shfl_xor_sync(0xffffffffu, dv, o);
        float att = dv + sd;
        att = att > 0.f ? att : 0.01f * att;        // leaky_relu(0.01)
        float w = __expf(att);
        if (valid) {
            red_add_v4(&acc[(size_t)sl * EMB + sub * 8],
                       make_float4(w * f0.x, w * f0.y, w * f0.z, w * f0.w));
            red_add_v4(&acc[(size_t)sl * EMB + sub * 8 + 4],
                       make_float4(w * f1.x, w * f1.y, w * f1.z, w * f1.w));
            if (sub == 0) atomicAdd(&den[sl], w);
        }
    }
}

// ---------------- k_final: fused per-row MLP, both sides ----------------
__device__ __forceinline__ float2 matvec64(const float* sWT, float xlo, float xhi,
                                           float b0, float b1, int lane) {
    float a0 = b0, a1 = b1;
    #pragma unroll
    for (int k = 0; k < 32; k++) {
        float xk = __shfl_sync(0xffffffffu, xlo, k);
        a0 += xk * sWT[k * 64 + lane];
        a1 += xk * sWT[k * 64 + lane + 32];
    }
    #pragma unroll
    for (int k = 0; k < 32; k++) {
        float xk = __shfl_sync(0xffffffffu, xhi, k);
        a0 += xk * sWT[(k + 32) * 64 + lane];
        a1 += xk * sWT[(k + 32) * 64 + lane + 32];
    }
    return make_float2(a0, a1);
}

__global__ void k_final(const int* __restrict__ u, const int* __restrict__ iid,
                        const float* __restrict__ user_emb, const float* __restrict__ item_emb,
                        const float* __restrict__ Ws_u, const float* __restrict__ bs_u,
                        const float* __restrict__ Ws_i, const float* __restrict__ bs_i,
                        const float* __restrict__ Wn_u, const float* __restrict__ bn_u,
                        const float* __restrict__ Wn_i, const float* __restrict__ bn_i,
                        const float* __restrict__ Wfc_u, const float* __restrict__ Wfc_i,
                        float* __restrict__ out) {
    int side = blockIdx.x >= FINAL_HALF;
    const int*   ids     = side ? iid      : u;
    const float* emb_tab = side ? item_emb : user_emb;
    const float* Ws  = side ? Ws_i  : Ws_u;
    const float* bs  = side ? bs_i  : bs_u;
    const float* Wn  = side ? Wn_i  : Wn_u;
    const float* bn  = side ? bn_i  : bn_u;
    const float* Wfc = side ? Wfc_i : Wfc_u;
    const int*   slot = side ? g_slot_i : g_slot_u;
    const float* den  = side ? g_den_i  : g_den_u;
    const float* acc  = side ? g_acc_i  : g_acc_u;
    const int col_off = side ? 64 : 0;

    extern __shared__ float sh[];
    float* sWsT  = sh;                  // 64*64
    float* sWnT  = sh + 64 * 64;        // 64*64
    float* sWfcT = sh + 2 * 64 * 64;    // 128*64
    for (int idx = threadIdx.x; idx < 64 * 64; idx += blockDim.x) {
        int j = idx >> 6, k = idx & 63;
        sWsT[k * 64 + j] = Ws[idx];
        sWnT[k * 64 + j] = Wn[idx];
    }
    for (int idx = threadIdx.x; idx < 64 * 128; idx += blockDim.x) {
        int j = idx >> 7, k = idx & 127;
        sWfcT[k * 64 + j] = Wfc[idx];
    }
    __syncthreads();

    int lane = threadIdx.x & 31;
    int warp = ((blockIdx.x - side * FINAL_HALF) * 256 + threadIdx.x) >> 5;
    int nwarps = (FINAL_HALF * 256) >> 5;
    float b_s0 = bs[lane], b_s1 = bs[lane + 32];
    float b_n0 = bn[lane], b_n1 = bn[lane + 32];

    for (int b = warp; b < BATCH; b += nwarps) {
        int node = ids[b];
        int s = slot[node];
        float dvn = den[s];
        float inv = dvn > 0.f ? 1.f / dvn : 0.f;   // empty segment -> h = 0 (matches ref)
        float hlo = acc[(size_t)s * EMB + lane] * inv;
        float hhi = acc[(size_t)s * EMB + 32 + lane] * inv;
        float elo = emb_tab[(size_t)node * EMB + lane];
        float ehi = emb_tab[(size_t)node * EMB + 32 + lane];

        float2 sf = matvec64(sWsT, elo, ehi, b_s0, b_s1, lane);
        float2 nb = matvec64(sWnT, hlo, hhi, b_n0, b_n1, lane);
        float sf0 = fmaxf(sf.x, 0.f), sf1 = fmaxf(sf.y, 0.f);
        float nb0 = fmaxf(nb.x, 0.f), nb1 = fmaxf(nb.y, 0.f);

        float a0 = 0.f, a1 = 0.f;
        #pragma unroll
        for (int k = 0; k < 32; k++) {
            float xk = __shfl_sync(0xffffffffu, sf0, k);
            a0 += xk * sWfcT[k * 64 + lane];
            a1 += xk * sWfcT[k * 64 + lane + 32];
        }
        #pragma unroll
        for (int k = 0; k < 32; k++) {
            float xk = __shfl_sync(0xffffffffu, sf1, k);
            a0 += xk * sWfcT[(k + 32) * 64 + lane];
            a1 += xk * sWfcT[(k + 32) * 64 + lane + 32];
        }
        #pragma unroll
        for (int k = 0; k < 32; k++) {
            float xk = __shfl_sync(0xffffffffu, nb0, k);
            a0 += xk * sWfcT[(k + 64) * 64 + lane];
            a1 += xk * sWfcT[(k + 64) * 64 + lane + 32];
        }
        #pragma unroll
        for (int k = 0; k < 32; k++) {
            float xk = __shfl_sync(0xffffffffu, nb1, k);
            a0 += xk * sWfcT[(k + 96) * 64 + lane];
            a1 += xk * sWfcT[(k + 96) * 64 + lane + 32];
        }
        out[(size_t)b * 128 + col_off + lane]      = fmaxf(a0, 0.f);
        out[(size_t)b * 128 + col_off + 32 + lane] = fmaxf(a1, 0.f);
    }
}

// ---------------- launch (single stream, plain launches only) ----------------
extern "C" void kernel_launch(void* const* d_in, const int* in_sizes, int n_in,
                              void* d_out, int out_size) {
    const float* user_emb = (const float*)d_in[0];
    const float* item_emb = (const float*)d_in[1];
    const float* Wa_u = (const float*)d_in[2];
    const float* Wa_i = (const float*)d_in[3];
    const float* Wfc_u = (const float*)d_in[4];
    const float* Wfc_i = (const float*)d_in[5];
    const float* Ws_u = (const float*)d_in[6];
    const float* bs_u = (const float*)d_in[7];
    const float* Ws_i = (const float*)d_in[8];
    const float* bs_i = (const float*)d_in[9];
    const float* Wn_u = (const float*)d_in[10];
    const float* bn_u = (const float*)d_in[11];
    const float* Wn_i = (const float*)d_in[12];
    const float* bn_i = (const float*)d_in[13];
    const int* u      = (const int*)d_in[14];
    const int* iid    = (const int*)d_in[15];
    const int* src_iu = (const int*)d_in[16];
    const int* dst_iu = (const int*)d_in[17];
    const int* src_ui = (const int*)d_in[18];
    const int* dst_ui = (const int*)d_in[19];
    float* out = (float*)d_out;

    const int SMEM_FINAL = (2 * 64 * 64 + 128 * 64) * sizeof(float);  // 65536 B
    static bool attr_set = false;
    if (!attr_set) {
        cudaFuncSetAttribute(k_final, cudaFuncAttributeMaxDynamicSharedMemorySize, SMEM_FINAL);
        attr_set = true;
    }

    k_init<<<512, 256>>>();
    k_slots<<<(2 * BATCH + 255) / 256, 256>>>(u, iid);
    k_bscores<<<1024, 256>>>(user_emb, item_emb, Wa_u, Wa_i, u, iid);
    k_scan<<<2 * GRID_SCAN_HALF, 256>>>(src_iu, dst_iu, src_ui, dst_ui);
    k_gather<<<2 * GRID_GATHER_HALF, 256>>>(item_emb, user_emb, Wa_u, Wa_i);
    k_final<<<2 * FINAL_HALF, 256, SMEM_FINAL>>>(u, iid, user_emb, item_emb,
                                                 Ws_u, bs_u, Ws_i, bs_i,
                                                 Wn_u, bn_u, Wn_i, bn_i,
                                                 Wfc_u, Wfc_i, out);
}

// round 6
// speedup vs baseline: 2.1451x; 1.9616x over previous
#include <cuda_runtime.h>
#include <cuda_bf16.h>
#include <cstdint>

#define EMB 64
#define NU 200000
#define NI 200000
#define NE 2000000
#define BATCH 16384

#define GRID_EDGE_HALF 7813     // ceil(NE/256)
#define SLOT_BLOCKS    128      // 2*BATCH/256
#define BSC_HALF       512      // 512*256/8 = 16384 rows
#define FINAL_HALF     128      // 128 blocks * 8 warps * 16 rows = 16384

// ---------------- static device scratch ----------------
__device__ int   g_slot_u[NU];
__device__ int   g_slot_i[NI];
__device__ float g_sdstb[2][BATCH];          // dst score per batch slot
__device__ float g_den_u[BATCH];
__device__ float g_den_i[BATCH];
__device__ __align__(16) float g_acc_u[BATCH * EMB];
__device__ __align__(16) float g_acc_i[BATCH * EMB];

__device__ __forceinline__ void red_add_v4(float* p, float4 v) {
    asm volatile("red.global.add.v4.f32 [%0], {%1,%2,%3,%4};"
                 :: "l"(p), "f"(v.x), "f"(v.y), "f"(v.z), "f"(v.w) : "memory");
}

// ---------------- k_init: init slot tables, zero den/acc ----------------
__global__ void k_init() {
    int t = blockIdx.x * blockDim.x + threadIdx.x;
    int stride = gridDim.x * blockDim.x;
    for (int n = t; n < NU; n += stride) g_slot_u[n] = -1;
    for (int n = t; n < NI; n += stride) g_slot_i[n] = -1;
    for (int n = t; n < BATCH; n += stride) { g_den_u[n] = 0.f; g_den_i[n] = 0.f; }
    float4 z = make_float4(0.f, 0.f, 0.f, 0.f);
    for (int n = t; n < BATCH * EMB / 4; n += stride) {
        ((float4*)g_acc_u)[n] = z;
        ((float4*)g_acc_i)[n] = z;
    }
}

// ---------------- k_prep: slot maps (blocks [0,128)) + batch dst scores ----------------
__global__ void k_prep(const int* __restrict__ u, const int* __restrict__ iid,
                       const float* __restrict__ user_emb, const float* __restrict__ item_emb,
                       const float* __restrict__ Wa_u, const float* __restrict__ Wa_i) {
    if (blockIdx.x < SLOT_BLOCKS) {
        int t = blockIdx.x * 256 + threadIdx.x;
        if (t < BATCH) {
            atomicCAS(&g_slot_u[u[t]], -1, t);
        } else {
            atomicCAS(&g_slot_i[iid[t - BATCH]], -1, t - BATCH);
        }
    } else {
        // dst scores: side0 = user_emb[u[b]].Wa_u[64:], side1 = item_emb[i[b]].Wa_i[64:]
        int blk = blockIdx.x - SLOT_BLOCKS;
        int side = blk >= BSC_HALF;
        const float* tab = side ? item_emb : user_emb;
        const float* wa  = (side ? Wa_i : Wa_u) + 64;
        const int*   ids = side ? iid : u;
        int t = (blk - side * BSC_HALF) * 256 + threadIdx.x;
        int b = t >> 3, sub = t & 7;
        float4 wv0 = ((const float4*)wa)[sub * 2];
        float4 wv1 = ((const float4*)wa)[sub * 2 + 1];
        int node = ids[b];
        const float4* fp = (const float4*)(tab + (size_t)node * EMB);
        float4 f0 = fp[sub * 2], f1 = fp[sub * 2 + 1];
        float dv = f0.x * wv0.x + f0.y * wv0.y + f0.z * wv0.z + f0.w * wv0.w
                 + f1.x * wv1.x + f1.y * wv1.y + f1.z * wv1.z + f1.w * wv1.w;
        #pragma unroll
        for (int o = 4; o; o >>= 1) dv += __shfl_xor_sync(0xffffffffu, dv, o);
        if (sub == 0) g_sdstb[side][b] = dv;
    }
}

// ---------------- k_edge: fused scan + gather + accumulate (both sides) ----------------
// Each warp scans 32 edges; active ones (~2.6/warp) processed 4-at-a-time, 8 lanes/edge.
// w = exp(leaky(row.wa_src + s_dst)); acc[slot] += w*row; den[slot] += w.
// No compaction, no global counters -> no hot-address atomics.
__global__ void k_edge(const int* __restrict__ src0, const int* __restrict__ dst0,
                       const int* __restrict__ src1, const int* __restrict__ dst1,
                       const float* __restrict__ item_emb, const float* __restrict__ user_emb,
                       const float* __restrict__ Wa_u, const float* __restrict__ Wa_i) {
    int side = blockIdx.x >= GRID_EDGE_HALF;
    const int*   src  = side ? src1     : src0;
    const int*   dst  = side ? dst1     : dst0;
    const int*   slot = side ? g_slot_i : g_slot_u;
    const float* feat = side ? user_emb : item_emb;   // source-node table
    const float* wa   = side ? Wa_i     : Wa_u;       // src half = wa[0:64]
    float*       den  = side ? g_den_i  : g_den_u;
    float*       acc  = side ? g_acc_i  : g_acc_u;
    const float* sdstb = g_sdstb[side];

    int lane = threadIdx.x & 31, sub = lane & 7;
    float4 wv0 = ((const float4*)wa)[sub * 2];        // this lane's 8-float chunk of wa_src
    float4 wv1 = ((const float4*)wa)[sub * 2 + 1];

    int e = (blockIdx.x - side * GRID_EDGE_HALF) * 256 + threadIdx.x;
    bool act = false;
    int s = -1, sr = 0;
    float sd = 0.f;
    if (e < NE) {
        int d = dst[e];
        s = slot[d];
        act = s >= 0;
        if (act) {
            sr = src[e];
            sd = sdstb[s];
        }
    }
    unsigned m = __ballot_sync(0xffffffffu, act);
    int cnt = __popc(m);
    for (int base = 0; base < cnt; base += 4) {
        int p = base + (lane >> 3);                   // which active edge this octet serves
        bool v = p < cnt;
        unsigned srclane = v ? __fns(m, 0, p + 1) : 0u;   // p-th set bit of mask
        int   sl2 = __shfl_sync(0xffffffffu, s,  srclane);
        int   sr2 = __shfl_sync(0xffffffffu, sr, srclane);
        float sd2 = __shfl_sync(0xffffffffu, sd, srclane);

        float4 f0 = make_float4(0.f, 0.f, 0.f, 0.f), f1 = f0;
        if (v) {
            const float4* fp = (const float4*)(feat + (size_t)sr2 * EMB);
            f0 = fp[sub * 2];
            f1 = fp[sub * 2 + 1];
        }
        float dv = f0.x * wv0.x + f0.y * wv0.y + f0.z * wv0.z + f0.w * wv0.w
                 + f1.x * wv1.x + f1.y * wv1.y + f1.z * wv1.z + f1.w * wv1.w;
        #pragma unroll
        for (int o = 4; o; o >>= 1) dv += __shfl_xor_sync(0xffffffffu, dv, o);
        float att = dv + sd2;
        att = att > 0.f ? att : 0.01f * att;          // leaky_relu(0.01)
        float w = __expf(att);
        if (v) {
            red_add_v4(&acc[(size_t)sl2 * EMB + sub * 8],
                       make_float4(w * f0.x, w * f0.y, w * f0.z, w * f0.w));
            red_add_v4(&acc[(size_t)sl2 * EMB + sub * 8 + 4],
                       make_float4(w * f1.x, w * f1.y, w * f1.z, w * f1.w));
            if (sub == 0) atomicAdd(&den[sl2], w);
        }
    }
}

// ---------------- k_final: fused MLP, 4-row-interleaved, 16 rows/warp ----------------
__global__ void k_final(const int* __restrict__ u, const int* __restrict__ iid,
                        const float* __restrict__ user_emb, const float* __restrict__ item_emb,
                        const float* __restrict__ Ws_u, const float* __restrict__ bs_u,
                        const float* __restrict__ Ws_i, const float* __restrict__ bs_i,
                        const float* __restrict__ Wn_u, const float* __restrict__ bn_u,
                        const float* __restrict__ Wn_i, const float* __restrict__ bn_i,
                        const float* __restrict__ Wfc_u, const float* __restrict__ Wfc_i,
                        float* __restrict__ out) {
    int side = blockIdx.x >= FINAL_HALF;
    const int*   ids     = side ? iid      : u;
    const float* emb_tab = side ? item_emb : user_emb;
    const float* Ws  = side ? Ws_i  : Ws_u;
    const float* bs  = side ? bs_i  : bs_u;
    const float* Wn  = side ? Wn_i  : Wn_u;
    const float* bn  = side ? bn_i  : bn_u;
    const float* Wfc = side ? Wfc_i : Wfc_u;
    const int*   slot = side ? g_slot_i : g_slot_u;
    const float* den  = side ? g_den_i  : g_den_u;
    const float* acc  = side ? g_acc_i  : g_acc_u;
    const int col_off = side ? 64 : 0;

    extern __shared__ float sh[];
    float* sWsT  = sh;                  // [k*64+j], 64x64
    float* sWnT  = sh + 64 * 64;
    float* sWfcT = sh + 2 * 64 * 64;    // [k*64+j], 128x64
    for (int idx = threadIdx.x; idx < 64 * 64; idx += blockDim.x) {
        int j = idx >> 6, k = idx & 63;
        sWsT[k * 64 + j] = Ws[idx];
        sWnT[k * 64 + j] = Wn[idx];
    }
    for (int idx = threadIdx.x; idx < 64 * 128; idx += blockDim.x) {
        int j = idx >> 7, k = idx & 127;
        sWfcT[k * 64 + j] = Wfc[idx];
    }
    __syncthreads();

    int lane = threadIdx.x & 31;
    int gw = ((blockIdx.x - side * FINAL_HALF) * 256 + threadIdx.x) >> 5;  // 0..1023
    float b_s0 = bs[lane], b_s1 = bs[lane + 32];
    float b_n0 = bn[lane], b_n1 = bn[lane + 32];

    for (int grp = 0; grp < 4; grp++) {
        int b0r = gw * 16 + grp * 4;
        float elo[4], ehi[4], hlo[4], hhi[4];
        #pragma unroll
        for (int r = 0; r < 4; r++) {
            int node = ids[b0r + r];
            int sl = slot[node];
            float dvn = den[sl];
            float inv = dvn > 0.f ? 1.f / dvn : 0.f;   // empty segment -> h = 0
            hlo[r] = acc[(size_t)sl * EMB + lane] * inv;
            hhi[r] = acc[(size_t)sl * EMB + 32 + lane] * inv;
            elo[r] = emb_tab[(size_t)node * EMB + lane];
            ehi[r] = emb_tab[(size_t)node * EMB + 32 + lane];
        }

        // stage 1: sf = relu(Ws.e + bs), nb = relu(Wn.h + bn), 4 rows interleaved
        float sA0[4], sA1[4], nA0[4], nA1[4];
        #pragma unroll
        for (int r = 0; r < 4; r++) { sA0[r] = b_s0; sA1[r] = b_s1; nA0[r] = b_n0; nA1[r] = b_n1; }
        #pragma unroll
        for (int k = 0; k < 32; k++) {
            float sw0 = sWsT[k * 64 + lane], sw1 = sWsT[k * 64 + lane + 32];
            float nw0 = sWnT[k * 64 + lane], nw1 = sWnT[k * 64 + lane + 32];
            #pragma unroll
            for (int r = 0; r < 4; r++) {
                float xe = __shfl_sync(0xffffffffu, elo[r], k);
                float xh = __shfl_sync(0xffffffffu, hlo[r], k);
                sA0[r] += xe * sw0; sA1[r] += xe * sw1;
                nA0[r] += xh * nw0; nA1[r] += xh * nw1;
            }
        }
        #pragma unroll
        for (int k = 0; k < 32; k++) {
            float sw0 = sWsT[(k + 32) * 64 + lane], sw1 = sWsT[(k + 32) * 64 + lane + 32];
            float nw0 = sWnT[(k + 32) * 64 + lane], nw1 = sWnT[(k + 32) * 64 + lane + 32];
            #pragma unroll
            for (int r = 0; r < 4; r++) {
                float xe = __shfl_sync(0xffffffffu, ehi[r], k);
                float xh = __shfl_sync(0xffffffffu, hhi[r], k);
                sA0[r] += xe * sw0; sA1[r] += xe * sw1;
                nA0[r] += xh * nw0; nA1[r] += xh * nw1;
            }
        }
        float sf0[4], sf1[4], nb0[4], nb1[4];
        #pragma unroll
        for (int r = 0; r < 4; r++) {
            sf0[r] = fmaxf(sA0[r], 0.f); sf1[r] = fmaxf(sA1[r], 0.f);
            nb0[r] = fmaxf(nA0[r], 0.f); nb1[r] = fmaxf(nA1[r], 0.f);
        }

        // stage 2: out = relu(Wfc . cat[sf, nb]), cat dims: sf0(0:32) sf1(32:64) nb0(64:96) nb1(96:128)
        float a0[4] = {0.f, 0.f, 0.f, 0.f}, a1[4] = {0.f, 0.f, 0.f, 0.f};
        #pragma unroll
        for (int k = 0; k < 32; k++) {
            float w00 = sWfcT[k * 64 + lane],          w01 = sWfcT[k * 64 + lane + 32];
            float w10 = sWfcT[(k + 32) * 64 + lane],   w11 = sWfcT[(k + 32) * 64 + lane + 32];
            float w20 = sWfcT[(k + 64) * 64 + lane],   w21 = sWfcT[(k + 64) * 64 + lane + 32];
            float w30 = sWfcT[(k + 96) * 64 + lane],   w31 = sWfcT[(k + 96) * 64 + lane + 32];
            #pragma unroll
            for (int r = 0; r < 4; r++) {
                float x0 = __shfl_sync(0xffffffffu, sf0[r], k);
                float x1 = __shfl_sync(0xffffffffu, sf1[r], k);
                float x2 = __shfl_sync(0xffffffffu, nb0[r], k);
                float x3 = __shfl_sync(0xffffffffu, nb1[r], k);
                a0[r] += x0 * w00 + x1 * w10 + x2 * w20 + x3 * w30;
                a1[r] += x0 * w01 + x1 * w11 + x2 * w21 + x3 * w31;
            }
        }
        #pragma unroll
        for (int r = 0; r < 4; r++) {
            out[(size_t)(b0r + r) * 128 + col_off + lane]      = fmaxf(a0[r], 0.f);
            out[(size_t)(b0r + r) * 128 + col_off + 32 + lane] = fmaxf(a1[r], 0.f);
        }
    }
}

// ---------------- launch (single stream, plain launches only) ----------------
extern "C" void kernel_launch(void* const* d_in, const int* in_sizes, int n_in,
                              void* d_out, int out_size) {
    const float* user_emb = (const float*)d_in[0];
    const float* item_emb = (const float*)d_in[1];
    const float* Wa_u = (const float*)d_in[2];
    const float* Wa_i = (const float*)d_in[3];
    const float* Wfc_u = (const float*)d_in[4];
    const float* Wfc_i = (const float*)d_in[5];
    const float* Ws_u = (const float*)d_in[6];
    const float* bs_u = (const float*)d_in[7];
    const float* Ws_i = (const float*)d_in[8];
    const float* bs_i = (const float*)d_in[9];
    const float* Wn_u = (const float*)d_in[10];
    const float* bn_u = (const float*)d_in[11];
    const float* Wn_i = (const float*)d_in[12];
    const float* bn_i = (const float*)d_in[13];
    const int* u      = (const int*)d_in[14];
    const int* iid    = (const int*)d_in[15];
    const int* src_iu = (const int*)d_in[16];
    const int* dst_iu = (const int*)d_in[17];
    const int* src_ui = (const int*)d_in[18];
    const int* dst_ui = (const int*)d_in[19];
    float* out = (float*)d_out;

    const int SMEM_FINAL = (2 * 64 * 64 + 128 * 64) * sizeof(float);  // 65536 B
    static bool attr_set = false;
    if (!attr_set) {
        cudaFuncSetAttribute(k_final, cudaFuncAttributeMaxDynamicSharedMemorySize, SMEM_FINAL);
        attr_set = true;
    }

    k_init<<<512, 256>>>();
    k_prep<<<SLOT_BLOCKS + 2 * BSC_HALF, 256>>>(u, iid, user_emb, item_emb, Wa_u, Wa_i);
    k_edge<<<2 * GRID_EDGE_HALF, 256>>>(src_iu, dst_iu, src_ui, dst_ui,
                                        item_emb, user_emb, Wa_u, Wa_i);
    k_final<<<2 * FINAL_HALF, 256, SMEM_FINAL>>>(u, iid, user_emb, item_emb,
                                                 Ws_u, bs_u, Ws_i, bs_i,
                                                 Wn_u, bn_u, Wn_i, bn_i,
                                                 Wfc_u, Wfc_i, out);
}

// round 9
// speedup vs baseline: 2.2054x; 1.0281x over previous
#include <cuda_runtime.h>
#include <cuda_bf16.h>
#include <cstdint>

#define EMB 64
#define NU 200000
#define NI 200000
#define NE 2000000
#define BATCH 16384

#define GRID_EDGE_HALF 7813     // ceil(NE/256)
#define SLOT_BLOCKS    128      // 2*BATCH/256
#define BSC_HALF       512      // 512*256/8 = 16384 rows
#define FINAL_HALF     256      // 256 blocks * 64 rows = 16384 per side

// ---------------- static device scratch ----------------
__device__ int   g_slot_u[NU];
__device__ int   g_slot_i[NI];
__device__ float g_sdstb[2][BATCH];          // dst score per batch slot
__device__ float g_den_u[BATCH];
__device__ float g_den_i[BATCH];
__device__ __align__(16) float g_acc_u[BATCH * EMB];
__device__ __align__(16) float g_acc_i[BATCH * EMB];

__device__ __forceinline__ void red_add_v4(float* p, float4 v) {
    asm volatile("red.global.add.v4.f32 [%0], {%1,%2,%3,%4};"
                 :: "l"(p), "f"(v.x), "f"(v.y), "f"(v.z), "f"(v.w) : "memory");
}

// ---------------- k_init ----------------
__global__ void k_init() {
    int t = blockIdx.x * blockDim.x + threadIdx.x;
    int stride = gridDim.x * blockDim.x;
    for (int n = t; n < NU; n += stride) g_slot_u[n] = -1;
    for (int n = t; n < NI; n += stride) g_slot_i[n] = -1;
    for (int n = t; n < BATCH; n += stride) { g_den_u[n] = 0.f; g_den_i[n] = 0.f; }
    float4 z = make_float4(0.f, 0.f, 0.f, 0.f);
    for (int n = t; n < BATCH * EMB / 4; n += stride) {
        ((float4*)g_acc_u)[n] = z;
        ((float4*)g_acc_i)[n] = z;
    }
}

// ---------------- k_prep: slot maps + batch dst scores ----------------
__global__ void k_prep(const int* __restrict__ u, const int* __restrict__ iid,
                       const float* __restrict__ user_emb, const float* __restrict__ item_emb,
                       const float* __restrict__ Wa_u, const float* __restrict__ Wa_i) {
    if (blockIdx.x < SLOT_BLOCKS) {
        int t = blockIdx.x * 256 + threadIdx.x;
        if (t < BATCH) {
            atomicCAS(&g_slot_u[u[t]], -1, t);
        } else {
            atomicCAS(&g_slot_i[iid[t - BATCH]], -1, t - BATCH);
        }
    } else {
        int blk = blockIdx.x - SLOT_BLOCKS;
        int side = blk >= BSC_HALF;
        const float* tab = side ? item_emb : user_emb;
        const float* wa  = (side ? Wa_i : Wa_u) + 64;
        const int*   ids = side ? iid : u;
        int t = (blk - side * BSC_HALF) * 256 + threadIdx.x;
        int b = t >> 3, sub = t & 7;
        float4 wv0 = ((const float4*)wa)[sub * 2];
        float4 wv1 = ((const float4*)wa)[sub * 2 + 1];
        int node = ids[b];
        const float4* fp = (const float4*)(tab + (size_t)node * EMB);
        float4 f0 = fp[sub * 2], f1 = fp[sub * 2 + 1];
        float dv = f0.x * wv0.x + f0.y * wv0.y + f0.z * wv0.z + f0.w * wv0.w
                 + f1.x * wv1.x + f1.y * wv1.y + f1.z * wv1.z + f1.w * wv1.w;
        #pragma unroll
        for (int o = 4; o; o >>= 1) dv += __shfl_xor_sync(0xffffffffu, dv, o);
        if (sub == 0) g_sdstb[side][b] = dv;
    }
}

// ---------------- k_edge: fused scan + gather + accumulate (both sides) ----------------
__global__ void k_edge(const int* __restrict__ src0, const int* __restrict__ dst0,
                       const int* __restrict__ src1, const int* __restrict__ dst1,
                       const float* __restrict__ item_emb, const float* __restrict__ user_emb,
                       const float* __restrict__ Wa_u, const float* __restrict__ Wa_i) {
    int side = blockIdx.x >= GRID_EDGE_HALF;
    const int*   src  = side ? src1     : src0;
    const int*   dst  = side ? dst1     : dst0;
    const int*   slot = side ? g_slot_i : g_slot_u;
    const float* feat = side ? user_emb : item_emb;   // source-node table
    const float* wa   = side ? Wa_i     : Wa_u;       // src half = wa[0:64]
    float*       den  = side ? g_den_i  : g_den_u;
    float*       acc  = side ? g_acc_i  : g_acc_u;
    const float* sdstb = g_sdstb[side];

    int lane = threadIdx.x & 31, sub = lane & 7;
    float4 wv0 = ((const float4*)wa)[sub * 2];
    float4 wv1 = ((const float4*)wa)[sub * 2 + 1];

    int e = (blockIdx.x - side * GRID_EDGE_HALF) * 256 + threadIdx.x;
    bool act = false;
    int s = -1, sr = 0;
    float sd = 0.f;
    if (e < NE) {
        int d = dst[e];
        s = slot[d];
        act = s >= 0;
        if (act) {
            sr = src[e];
            sd = sdstb[s];
        }
    }
    unsigned m = __ballot_sync(0xffffffffu, act);
    int cnt = __popc(m);
    for (int base = 0; base < cnt; base += 4) {
        int p = base + (lane >> 3);
        bool v = p < cnt;
        unsigned srclane = v ? __fns(m, 0, p + 1) : 0u;
        int   sl2 = __shfl_sync(0xffffffffu, s,  srclane);
        int   sr2 = __shfl_sync(0xffffffffu, sr, srclane);
        float sd2 = __shfl_sync(0xffffffffu, sd, srclane);

        float4 f0 = make_float4(0.f, 0.f, 0.f, 0.f), f1 = f0;
        if (v) {
            const float4* fp = (const float4*)(feat + (size_t)sr2 * EMB);
            f0 = fp[sub * 2];
            f1 = fp[sub * 2 + 1];
        }
        float dv = f0.x * wv0.x + f0.y * wv0.y + f0.z * wv0.z + f0.w * wv0.w
                 + f1.x * wv1.x + f1.y * wv1.y + f1.z * wv1.z + f1.w * wv1.w;
        #pragma unroll
        for (int o = 4; o; o >>= 1) dv += __shfl_xor_sync(0xffffffffu, dv, o);
        float att = dv + sd2;
        att = att > 0.f ? att : 0.01f * att;          // leaky_relu(0.01)
        float w = __expf(att);
        if (v) {
            red_add_v4(&acc[(size_t)sl2 * EMB + sub * 8],
                       make_float4(w * f0.x, w * f0.y, w * f0.z, w * f0.w));
            red_add_v4(&acc[(size_t)sl2 * EMB + sub * 8 + 4],
                       make_float4(w * f1.x, w * f1.y, w * f1.z, w * f1.w));
            if (sub == 0) atomicAdd(&den[sl2], w);
        }
    }
}

// ---------------- k_final v2: smem-tiled register-blocked GEMM, 64 rows/block --------
// smem (floats, stride-68 rows for conflict-free float4):
//   sX  @ 0     : 64x68  emb tile     -> after stage1: sf tile
//   sH  @ 4352  : 64x68  h tile       -> after stage1: nb tile
//   sW  @ 8704  : stage1 Ws(64x68) + Wn(64x68) native [out][k]; stage2 Wfc 64x132
#define XS 68
#define WFS 132
#define SM_X 0
#define SM_H 4352
#define SM_W 8704
#define SMEM_FINAL_F (8704 + 2 * 4352)        // 17408 floats = 69632 B

__global__ __launch_bounds__(256)
void k_final(const int* __restrict__ u, const int* __restrict__ iid,
             const float* __restrict__ user_emb, const float* __restrict__ item_emb,
             const float* __restrict__ Ws_u, const float* __restrict__ bs_u,
             const float* __restrict__ Ws_i, const float* __restrict__ bs_i,
             const float* __restrict__ Wn_u, const float* __restrict__ bn_u,
             const float* __restrict__ Wn_i, const float* __restrict__ bn_i,
             const float* __restrict__ Wfc_u, const float* __restrict__ Wfc_i,
             float* __restrict__ out) {
    int side = blockIdx.x >= FINAL_HALF;
    const int*   ids     = side ? iid      : u;
    const float* emb_tab = side ? item_emb : user_emb;
    const float* Ws  = side ? Ws_i  : Ws_u;
    const float* bs  = side ? bs_i  : bs_u;
    const float* Wn  = side ? Wn_i  : Wn_u;
    const float* bn  = side ? bn_i  : bn_u;
    const float* Wfc = side ? Wfc_i : Wfc_u;
    const int*   slot = side ? g_slot_i : g_slot_u;
    const float* den  = side ? g_den_i  : g_den_u;
    const float* acc  = side ? g_acc_i  : g_acc_u;
    const int col_off = side ? 64 : 0;

    extern __shared__ float sh[];
    __shared__ int   sNode[64];
    __shared__ int   sSl[64];
    __shared__ float sInv[64];

    int tid = threadIdx.x;
    int base = (blockIdx.x - side * FINAL_HALF) * 64;

    // row metadata
    if (tid < 64) {
        int node = ids[base + tid];
        int sl = slot[node];
        float dvn = den[sl];
        sNode[tid] = node;
        sSl[tid] = sl;
        sInv[tid] = dvn > 0.f ? 1.f / dvn : 0.f;    // empty segment -> h = 0
    }
    // stage-1 weights, native [out][k] layout, stride 68 (straight copy, no conflicts)
    {
        const float4* Wsv = (const float4*)Ws;
        const float4* Wnv = (const float4*)Wn;
        for (int v = tid; v < 1024; v += 256) {
            int j = v >> 4, q = v & 15;
            *(float4*)&sh[SM_W + j * XS + q * 4]        = Wsv[v];
            *(float4*)&sh[SM_W + 4352 + j * XS + q * 4] = Wnv[v];
        }
    }
    __syncthreads();

    // gather X (emb) and H (acc/den) tiles
    for (int v = tid; v < 1024; v += 256) {
        int r = v >> 4, q = v & 15;
        float4 ev = ((const float4*)emb_tab)[(size_t)sNode[r] * 16 + q];
        float4 hv = ((const float4*)acc)[(size_t)sSl[r] * 16 + q];
        float inv = sInv[r];
        *(float4*)&sh[SM_X + r * XS + q * 4] = ev;
        *(float4*)&sh[SM_H + r * XS + q * 4] =
            make_float4(hv.x * inv, hv.y * inv, hv.z * inv, hv.w * inv);
    }
    __syncthreads();

    // ---- stage 1: half 0 -> sf = relu(X.Ws^T + bs); half 1 -> nb = relu(H.Wn^T + bn)
    {
        int half = tid >> 7;
        int t = tid & 127;
        int ty = t >> 4, tx = t & 15;                 // rows ty*8..+7, cols tx*4..+3
        const float* sXH = sh + (half ? SM_H : SM_X);
        const float* sW  = sh + SM_W + half * 4352;
        float a[8][4];
        #pragma unroll
        for (int i = 0; i < 8; i++)
            #pragma unroll
            for (int j = 0; j < 4; j++) a[i][j] = 0.f;

        #pragma unroll
        for (int kc = 0; kc < 16; kc++) {
            float4 xv[8], wv[4];
            #pragma unroll
            for (int i = 0; i < 8; i++)
                xv[i] = *(const float4*)&sXH[(ty * 8 + i) * XS + kc * 4];
            #pragma unroll
            for (int j = 0; j < 4; j++)
                wv[j] = *(const float4*)&sW[(tx * 4 + j) * XS + kc * 4];
            #pragma unroll
            for (int i = 0; i < 8; i++)
                #pragma unroll
                for (int j = 0; j < 4; j++)
                    a[i][j] += xv[i].x * wv[j].x + xv[i].y * wv[j].y
                             + xv[i].z * wv[j].z + xv[i].w * wv[j].w;
        }
        const float* bias = half ? bn : bs;
        float4 bv = *(const float4*)&bias[tx * 4];
        __syncthreads();                               // all stage-1 reads done
        float* dstM = sh + (half ? SM_H : SM_X);
        #pragma unroll
        for (int i = 0; i < 8; i++) {
            float4 r;
            r.x = fmaxf(a[i][0] + bv.x, 0.f);
            r.y = fmaxf(a[i][1] + bv.y, 0.f);
            r.z = fmaxf(a[i][2] + bv.z, 0.f);
            r.w = fmaxf(a[i][3] + bv.w, 0.f);
            *(float4*)&dstM[(ty * 8 + i) * XS + tx * 4] = r;
        }
    }
    // stage-2 weights: Wfc [64][128] native, stride 132
    {
        const float4* Wv = (const float4*)Wfc;
        for (int v = tid; v < 2048; v += 256) {
            int j = v >> 5, q = v & 31;
            *(float4*)&sh[SM_W + j * WFS + q * 4] = Wv[v];
        }
    }
    __syncthreads();

    // ---- stage 2: out = relu([sf|nb] . Wfc^T), 4x4 tiles, K=128
    {
        int ty = tid >> 4, tx = tid & 15;             // rows ty*4..+3, cols tx*4..+3
        float a[4][4];
        #pragma unroll
        for (int i = 0; i < 4; i++)
            #pragma unroll
            for (int j = 0; j < 4; j++) a[i][j] = 0.f;

        #pragma unroll
        for (int kc = 0; kc < 32; kc++) {
            const float* sxb = sh + (kc < 16 ? SM_X : SM_H);
            int kq = (kc & 15) * 4;
            float4 xv[4], wv[4];
            #pragma unroll
            for (int i = 0; i < 4; i++)
                xv[i] = *(const float4*)&sxb[(ty * 4 + i) * XS + kq];
            #pragma unroll
            for (int j = 0; j < 4; j++)
                wv[j] = *(const float4*)&sh[SM_W + (tx * 4 + j) * WFS + kc * 4];
            #pragma unroll
            for (int i = 0; i < 4; i++)
                #pragma unroll
                for (int j = 0; j < 4; j++)
                    a[i][j] += xv[i].x * wv[j].x + xv[i].y * wv[j].y
                             + xv[i].z * wv[j].z + xv[i].w * wv[j].w;
        }
        #pragma unroll
        for (int i = 0; i < 4; i++) {
            float4 r;
            r.x = fmaxf(a[i][0], 0.f);
            r.y = fmaxf(a[i][1], 0.f);
            r.z = fmaxf(a[i][2], 0.f);
            r.w = fmaxf(a[i][3], 0.f);
            *(float4*)&out[(size_t)(base + ty * 4 + i) * 128 + col_off + tx * 4] = r;
        }
    }
}

// ---------------- launch (single stream, plain launches only) ----------------
extern "C" void kernel_launch(void* const* d_in, const int* in_sizes, int n_in,
                              void* d_out, int out_size) {
    const float* user_emb = (const float*)d_in[0];
    const float* item_emb = (const float*)d_in[1];
    const float* Wa_u = (const float*)d_in[2];
    const float* Wa_i = (const float*)d_in[3];
    const float* Wfc_u = (const float*)d_in[4];
    const float* Wfc_i = (const float*)d_in[5];
    const float* Ws_u = (const float*)d_in[6];
    const float* bs_u = (const float*)d_in[7];
    const float* Ws_i = (const float*)d_in[8];
    const float* bs_i = (const float*)d_in[9];
    const float* Wn_u = (const float*)d_in[10];
    const float* bn_u = (const float*)d_in[11];
    const float* Wn_i = (const float*)d_in[12];
    const float* bn_i = (const float*)d_in[13];
    const int* u      = (const int*)d_in[14];
    const int* iid    = (const int*)d_in[15];
    const int* src_iu = (const int*)d_in[16];
    const int* dst_iu = (const int*)d_in[17];
    const int* src_ui = (const int*)d_in[18];
    const int* dst_ui = (const int*)d_in[19];
    float* out = (float*)d_out;

    const int SMEM_FINAL = SMEM_FINAL_F * sizeof(float);  // 69632 B
    static bool attr_set = false;
    if (!attr_set) {
        cudaFuncSetAttribute(k_final, cudaFuncAttributeMaxDynamicSharedMemorySize, SMEM_FINAL);
        attr_set = true;
    }

    k_init<<<512, 256>>>();
    k_prep<<<SLOT_BLOCKS + 2 * BSC_HALF, 256>>>(u, iid, user_emb, item_emb, Wa_u, Wa_i);
    k_edge<<<2 * GRID_EDGE_HALF, 256>>>(src_iu, dst_iu, src_ui, dst_ui,
                                        item_emb, user_emb, Wa_u, Wa_i);
    k_final<<<2 * FINAL_HALF, 256, SMEM_FINAL>>>(u, iid, user_emb, item_emb,
                                                 Ws_u, bs_u, Ws_i, bs_i,
                                                 Wn_u, bn_u, Wn_i, bn_i,
                                                 Wfc_u, Wfc_i, out);
}

// round 11
// speedup vs baseline: 2.8148x; 1.2763x over previous
#include <cuda_runtime.h>
#include <cuda_bf16.h>
#include <cstdint>

#define EMB 64
#define NU 200000
#define NI 200000
#define NE 2000000
#define BATCH 16384

#define GRID_EDGE_HALF 7813     // ceil(NE/256)
#define SLOT_BLOCKS    128      // 2*BATCH/256
#define BSC_HALF       512      // 512*256/8 = 16384 rows
#define FINAL_HALF     256      // 256 blocks * 64 rows = 16384 per side

// ---------------- static device scratch ----------------
__device__ int   g_slot_u[NU];
__device__ int   g_slot_i[NI];
__device__ float g_sdstb[2][BATCH];          // dst score per batch slot
__device__ float g_den_u[BATCH];
__device__ float g_den_i[BATCH];
__device__ __align__(16) float g_acc_u[BATCH * EMB];
__device__ __align__(16) float g_acc_i[BATCH * EMB];

__device__ __forceinline__ void red_add_v4(float* p, float4 v) {
    asm volatile("red.global.add.v4.f32 [%0], {%1,%2,%3,%4};"
                 :: "l"(p), "f"(v.x), "f"(v.y), "f"(v.z), "f"(v.w) : "memory");
}

// ---------------- k_init ----------------
__global__ void k_init() {
    int t = blockIdx.x * blockDim.x + threadIdx.x;
    int stride = gridDim.x * blockDim.x;
    for (int n = t; n < NU; n += stride) g_slot_u[n] = -1;
    for (int n = t; n < NI; n += stride) g_slot_i[n] = -1;
    for (int n = t; n < BATCH; n += stride) { g_den_u[n] = 0.f; g_den_i[n] = 0.f; }
    float4 z = make_float4(0.f, 0.f, 0.f, 0.f);
    for (int n = t; n < BATCH * EMB / 4; n += stride) {
        ((float4*)g_acc_u)[n] = z;
        ((float4*)g_acc_i)[n] = z;
    }
}

// ---------------- k_prep: slot maps + batch dst scores ----------------
__global__ void k_prep(const int* __restrict__ u, const int* __restrict__ iid,
                       const float* __restrict__ user_emb, const float* __restrict__ item_emb,
                       const float* __restrict__ Wa_u, const float* __restrict__ Wa_i) {
    if (blockIdx.x < SLOT_BLOCKS) {
        int t = blockIdx.x * 256 + threadIdx.x;
        if (t < BATCH) {
            atomicCAS(&g_slot_u[u[t]], -1, t);
        } else {
            atomicCAS(&g_slot_i[iid[t - BATCH]], -1, t - BATCH);
        }
    } else {
        int blk = blockIdx.x - SLOT_BLOCKS;
        int side = blk >= BSC_HALF;
        const float* tab = side ? item_emb : user_emb;
        const float* wa  = (side ? Wa_i : Wa_u) + 64;
        const int*   ids = side ? iid : u;
        int t = (blk - side * BSC_HALF) * 256 + threadIdx.x;
        int b = t >> 3, sub = t & 7;
        float4 wv0 = ((const float4*)wa)[sub * 2];
        float4 wv1 = ((const float4*)wa)[sub * 2 + 1];
        int node = ids[b];
        const float4* fp = (const float4*)(tab + (size_t)node * EMB);
        float4 f0 = fp[sub * 2], f1 = fp[sub * 2 + 1];
        float dv = f0.x * wv0.x + f0.y * wv0.y + f0.z * wv0.z + f0.w * wv0.w
                 + f1.x * wv1.x + f1.y * wv1.y + f1.z * wv1.z + f1.w * wv1.w;
        #pragma unroll
        for (int o = 4; o; o >>= 1) dv += __shfl_xor_sync(0xffffffffu, dv, o);
        if (sub == 0) g_sdstb[side][b] = dv;
    }
}

// ---------------- k_edge: fused scan + gather + accumulate (both sides) ----------------
__global__ void k_edge(const int* __restrict__ src0, const int* __restrict__ dst0,
                       const int* __restrict__ src1, const int* __restrict__ dst1,
                       const float* __restrict__ item_emb, const float* __restrict__ user_emb,
                       const float* __restrict__ Wa_u, const float* __restrict__ Wa_i) {
    int side = blockIdx.x >= GRID_EDGE_HALF;
    const int*   src  = side ? src1     : src0;
    const int*   dst  = side ? dst1     : dst0;
    const int*   slot = side ? g_slot_i : g_slot_u;
    const float* feat = side ? user_emb : item_emb;   // source-node table
    const float* wa   = side ? Wa_i     : Wa_u;       // src half = wa[0:64]
    float*       den  = side ? g_den_i  : g_den_u;
    float*       acc  = side ? g_acc_i  : g_acc_u;
    const float* sdstb = g_sdstb[side];

    int lane = threadIdx.x & 31, sub = lane & 7;
    float4 wv0 = ((const float4*)wa)[sub * 2];
    float4 wv1 = ((const float4*)wa)[sub * 2 + 1];

    int e = (blockIdx.x - side * GRID_EDGE_HALF) * 256 + threadIdx.x;
    bool act = false;
    int s = -1, sr = 0;
    float sd = 0.f;
    if (e < NE) {
        int d = dst[e];
        s = slot[d];
        act = s >= 0;
        if (act) {
            sr = src[e];
            sd = sdstb[s];
        }
    }
    unsigned m = __ballot_sync(0xffffffffu, act);
    int cnt = __popc(m);
    for (int base = 0; base < cnt; base += 4) {
        int p = base + (lane >> 3);
        bool v = p < cnt;
        unsigned srclane = v ? __fns(m, 0, p + 1) : 0u;
        int   sl2 = __shfl_sync(0xffffffffu, s,  srclane);
        int   sr2 = __shfl_sync(0xffffffffu, sr, srclane);
        float sd2 = __shfl_sync(0xffffffffu, sd, srclane);

        float4 f0 = make_float4(0.f, 0.f, 0.f, 0.f), f1 = f0;
        if (v) {
            const float4* fp = (const float4*)(feat + (size_t)sr2 * EMB);
            f0 = fp[sub * 2];
            f1 = fp[sub * 2 + 1];
        }
        float dv = f0.x * wv0.x + f0.y * wv0.y + f0.z * wv0.z + f0.w * wv0.w
                 + f1.x * wv1.x + f1.y * wv1.y + f1.z * wv1.z + f1.w * wv1.w;
        #pragma unroll
        for (int o = 4; o; o >>= 1) dv += __shfl_xor_sync(0xffffffffu, dv, o);
        float att = dv + sd2;
        att = att > 0.f ? att : 0.01f * att;          // leaky_relu(0.01)
        float w = __expf(att);
        if (v) {
            red_add_v4(&acc[(size_t)sl2 * EMB + sub * 8],
                       make_float4(w * f0.x, w * f0.y, w * f0.z, w * f0.w));
            red_add_v4(&acc[(size_t)sl2 * EMB + sub * 8 + 4],
                       make_float4(w * f1.x, w * f1.y, w * f1.z, w * f1.w));
            if (sub == 0) atomicAdd(&den[sl2], w);
        }
    }
}

// ---------------- k_final v3: transposed-weight smem GEMM, conflict-free ----------------
// smem (floats, stride 68):
//   sX @ 0    : 64x68  emb tile [row][k]   -> after stage1: sf tile
//   sH @ 4352 : 64x68  h tile   [row][k]   -> after stage1: nb tile
//   sW @ 8704 : stage1 WsT(64x68)+WnT(64x68) as [k][out]; stage2 WfcT 128x68 [k][out]
// LDS patterns: x reads/writes vary only in 2 row values per warp (broadcast);
// weight reads vary in tx*4 column within one row (consecutive -> 2-phase optimal).
// Weight transpose at load: thread j=v&63 scatters 4 scalars; store bank = 16*k4+4c+j
// spans all 32 banks across lanes -> conflict-free.
#define XS 68
#define SM_X 0
#define SM_H 4352
#define SM_W 8704
#define SMEM_FINAL_F (8704 + 2 * 4352)        // 17408 floats = 69632 B

__global__ __launch_bounds__(256)
void k_final(const int* __restrict__ u, const int* __restrict__ iid,
             const float* __restrict__ user_emb, const float* __restrict__ item_emb,
             const float* __restrict__ Ws_u, const float* __restrict__ bs_u,
             const float* __restrict__ Ws_i, const float* __restrict__ bs_i,
             const float* __restrict__ Wn_u, const float* __restrict__ bn_u,
             const float* __restrict__ Wn_i, const float* __restrict__ bn_i,
             const float* __restrict__ Wfc_u, const float* __restrict__ Wfc_i,
             float* __restrict__ out) {
    int side = blockIdx.x >= FINAL_HALF;
    const int*   ids     = side ? iid      : u;
    const float* emb_tab = side ? item_emb : user_emb;
    const float* Ws  = side ? Ws_i  : Ws_u;
    const float* bs  = side ? bs_i  : bs_u;
    const float* Wn  = side ? Wn_i  : Wn_u;
    const float* bn  = side ? bn_i  : bn_u;
    const float* Wfc = side ? Wfc_i : Wfc_u;
    const int*   slot = side ? g_slot_i : g_slot_u;
    const float* den  = side ? g_den_i  : g_den_u;
    const float* acc  = side ? g_acc_i  : g_acc_u;
    const int col_off = side ? 64 : 0;

    extern __shared__ float sh[];
    __shared__ int   sNode[64];
    __shared__ int   sSl[64];
    __shared__ float sInv[64];

    int tid = threadIdx.x;
    int base = (blockIdx.x - side * FINAL_HALF) * 64;

    // row metadata
    if (tid < 64) {
        int node = ids[base + tid];
        int sl = slot[node];
        float dvn = den[sl];
        sNode[tid] = node;
        sSl[tid] = sl;
        sInv[tid] = dvn > 0.f ? 1.f / dvn : 0.f;    // empty segment -> h = 0
    }
    // stage-1 weights, transposed to [k][out], stride 68
    {
        const float4* Wsv = (const float4*)Ws;
        const float4* Wnv = (const float4*)Wn;
        for (int v = tid; v < 1024; v += 256) {
            int j = v & 63, k4 = v >> 6;             // lanes: consecutive j
            float4 a = Wsv[j * 16 + k4];
            float4 b = Wnv[j * 16 + k4];
            sh[SM_W + (k4 * 4 + 0) * XS + j] = a.x;
            sh[SM_W + (k4 * 4 + 1) * XS + j] = a.y;
            sh[SM_W + (k4 * 4 + 2) * XS + j] = a.z;
            sh[SM_W + (k4 * 4 + 3) * XS + j] = a.w;
            sh[SM_W + 4352 + (k4 * 4 + 0) * XS + j] = b.x;
            sh[SM_W + 4352 + (k4 * 4 + 1) * XS + j] = b.y;
            sh[SM_W + 4352 + (k4 * 4 + 2) * XS + j] = b.z;
            sh[SM_W + 4352 + (k4 * 4 + 3) * XS + j] = b.w;
        }
    }
    __syncthreads();

    // gather X (emb) and H (acc/den) tiles, [row][k]
    for (int v = tid; v < 1024; v += 256) {
        int r = v >> 4, q = v & 15;
        float4 ev = ((const float4*)emb_tab)[(size_t)sNode[r] * 16 + q];
        float4 hv = ((const float4*)acc)[(size_t)sSl[r] * 16 + q];
        float inv = sInv[r];
        *(float4*)&sh[SM_X + r * XS + q * 4] = ev;
        *(float4*)&sh[SM_H + r * XS + q * 4] =
            make_float4(hv.x * inv, hv.y * inv, hv.z * inv, hv.w * inv);
    }
    __syncthreads();

    // ---- stage 1: half 0 -> sf = relu(X.Ws^T + bs); half 1 -> nb = relu(H.Wn^T + bn)
    {
        int half = tid >> 7;
        int t = tid & 127;
        int ty = t >> 4, tx = t & 15;                 // rows ty*8..+7, cols tx*4..+3
        const float* sXH = sh + (half ? SM_H : SM_X);
        const float* sWT = sh + SM_W + half * 4352;
        float a[8][4];
        #pragma unroll
        for (int i = 0; i < 8; i++)
            #pragma unroll
            for (int j = 0; j < 4; j++) a[i][j] = 0.f;

        #pragma unroll
        for (int kc = 0; kc < 16; kc++) {
            float4 xv[8], wt[4];
            #pragma unroll
            for (int i = 0; i < 8; i++)
                xv[i] = *(const float4*)&sXH[(ty * 8 + i) * XS + kc * 4];   // broadcast
            #pragma unroll
            for (int c = 0; c < 4; c++)
                wt[c] = *(const float4*)&sWT[(kc * 4 + c) * XS + tx * 4];   // in-row walk
            #pragma unroll
            for (int i = 0; i < 8; i++) {
                a[i][0] += xv[i].x * wt[0].x + xv[i].y * wt[1].x + xv[i].z * wt[2].x + xv[i].w * wt[3].x;
                a[i][1] += xv[i].x * wt[0].y + xv[i].y * wt[1].y + xv[i].z * wt[2].y + xv[i].w * wt[3].y;
                a[i][2] += xv[i].x * wt[0].z + xv[i].y * wt[1].z + xv[i].z * wt[2].z + xv[i].w * wt[3].z;
                a[i][3] += xv[i].x * wt[0].w + xv[i].y * wt[1].w + xv[i].z * wt[2].w + xv[i].w * wt[3].w;
            }
        }
        const float* bias = half ? bn : bs;
        float4 bv = *(const float4*)&bias[tx * 4];
        __syncthreads();                               // all stage-1 smem reads done
        float* dstM = sh + (half ? SM_H : SM_X);
        #pragma unroll
        for (int i = 0; i < 8; i++) {
            float4 r;
            r.x = fmaxf(a[i][0] + bv.x, 0.f);
            r.y = fmaxf(a[i][1] + bv.y, 0.f);
            r.z = fmaxf(a[i][2] + bv.z, 0.f);
            r.w = fmaxf(a[i][3] + bv.w, 0.f);
            *(float4*)&dstM[(ty * 8 + i) * XS + tx * 4] = r;
        }
    }
    // stage-2 weights: WfcT [k=128][out=64], stride 68
    {
        const float4* Wv = (const float4*)Wfc;
        for (int v = tid; v < 2048; v += 256) {
            int j = v & 63, k4 = v >> 6;              // k4 0..31
            float4 w = Wv[j * 32 + k4];
            sh[SM_W + (k4 * 4 + 0) * XS + j] = w.x;
            sh[SM_W + (k4 * 4 + 1) * XS + j] = w.y;
            sh[SM_W + (k4 * 4 + 2) * XS + j] = w.z;
            sh[SM_W + (k4 * 4 + 3) * XS + j] = w.w;
        }
    }
    __syncthreads();

    // ---- stage 2: out = relu([sf|nb] . Wfc^T), 4x4 tiles, K=128
    {
        int ty = tid >> 4, tx = tid & 15;             // rows ty*4..+3, cols tx*4..+3
        float a[4][4];
        #pragma unroll
        for (int i = 0; i < 4; i++)
            #pragma unroll
            for (int j = 0; j < 4; j++) a[i][j] = 0.f;

        #pragma unroll
        for (int kc = 0; kc < 32; kc++) {
            const float* sxb = sh + (kc < 16 ? SM_X : SM_H);
            int kq = (kc & 15) * 4;
            float4 xv[4], wt[4];
            #pragma unroll
            for (int i = 0; i < 4; i++)
                xv[i] = *(const float4*)&sxb[(ty * 4 + i) * XS + kq];       // broadcast
            #pragma unroll
            for (int c = 0; c < 4; c++)
                wt[c] = *(const float4*)&sh[SM_W + (kc * 4 + c) * XS + tx * 4];  // in-row walk
            #pragma unroll
            for (int i = 0; i < 4; i++) {
                a[i][0] += xv[i].x * wt[0].x + xv[i].y * wt[1].x + xv[i].z * wt[2].x + xv[i].w * wt[3].x;
                a[i][1] += xv[i].x * wt[0].y + xv[i].y * wt[1].y + xv[i].z * wt[2].y + xv[i].w * wt[3].y;
                a[i][2] += xv[i].x * wt[0].z + xv[i].y * wt[1].z + xv[i].z * wt[2].z + xv[i].w * wt[3].z;
                a[i][3] += xv[i].x * wt[0].w + xv[i].y * wt[1].w + xv[i].z * wt[2].w + xv[i].w * wt[3].w;
            }
        }
        #pragma unroll
        for (int i = 0; i < 4; i++) {
            float4 r;
            r.x = fmaxf(a[i][0], 0.f);
            r.y = fmaxf(a[i][1], 0.f);
            r.z = fmaxf(a[i][2], 0.f);
            r.w = fmaxf(a[i][3], 0.f);
            *(float4*)&out[(size_t)(base + ty * 4 + i) * 128 + col_off + tx * 4] = r;
        }
    }
}

// ---------------- launch (single stream, plain launches only) ----------------
extern "C" void kernel_launch(void* const* d_in, const int* in_sizes, int n_in,
                              void* d_out, int out_size) {
    const float* user_emb = (const float*)d_in[0];
    const float* item_emb = (const float*)d_in[1];
    const float* Wa_u = (const float*)d_in[2];
    const float* Wa_i = (const float*)d_in[3];
    const float* Wfc_u = (const float*)d_in[4];
    const float* Wfc_i = (const float*)d_in[5];
    const float* Ws_u = (const float*)d_in[6];
    const float* bs_u = (const float*)d_in[7];
    const float* Ws_i = (const float*)d_in[8];
    const float* bs_i = (const float*)d_in[9];
    const float* Wn_u = (const float*)d_in[10];
    const float* bn_u = (const float*)d_in[11];
    const float* Wn_i = (const float*)d_in[12];
    const float* bn_i = (const float*)d_in[13];
    const int* u      = (const int*)d_in[14];
    const int* iid    = (const int*)d_in[15];
    const int* src_iu = (const int*)d_in[16];
    const int* dst_iu = (const int*)d_in[17];
    const int* src_ui = (const int*)d_in[18];
    const int* dst_ui = (const int*)d_in[19];
    float* out = (float*)d_out;

    const int SMEM_FINAL = SMEM_FINAL_F * sizeof(float);  // 69632 B
    static bool attr_set = false;
    if (!attr_set) {
        cudaFuncSetAttribute(k_final, cudaFuncAttributeMaxDynamicSharedMemorySize, SMEM_FINAL);
        attr_set = true;
    }

    k_init<<<512, 256>>>();
    k_prep<<<SLOT_BLOCKS + 2 * BSC_HALF, 256>>>(u, iid, user_emb, item_emb, Wa_u, Wa_i);
    k_edge<<<2 * GRID_EDGE_HALF, 256>>>(src_iu, dst_iu, src_ui, dst_ui,
                                        item_emb, user_emb, Wa_u, Wa_i);
    k_final<<<2 * FINAL_HALF, 256, SMEM_FINAL>>>(u, iid, user_emb, item_emb,
                                                 Ws_u, bs_u, Ws_i, bs_i,
                                                 Wn_u, bn_u, Wn_i, bn_i,
                                                 Wfc_u, Wfc_i, out);
}